// round 15
// baseline (speedup 1.0000x reference)
#include <cuda_runtime.h>
#include <math.h>
#include <stdint.h>

#define DZ 64
#define DC 32
#define TILE 128
#define THREADS 256
#define ZS_STRIDE 68          // floats/row: conflict-free A-frag loads (4g+a distinct)
#define BS_STRIDE 68          // bank(4g+a) all-distinct for B loads
#define TH_FAST 2.5e-4f       // tf32 -> exact-fp32 re-decide trigger (proven R7-R14)
#define TH_MED  4e-6f         // fp32 -> exact-double re-decide trigger (proven R6-R14)

// dynamic smem layout (bytes)
#define SM_MBAR   0           // 2 x u64
#define SM_BS     128         // 31*68*4 = 8432
#define SM_ZS0    8576        // 128*68*4 = 34816  (128B-aligned)
#define SM_ZS1    (8576 + 34816)
#define SM_TOTAL  (8576 + 2 * 34816)   // 78208

__device__ __forceinline__ uint32_t to_tf32(float f) {
    uint32_t r;
    asm("cvt.rna.tf32.f32 %0, %1;" : "=r"(r) : "f"(f));
    return r;
}

__device__ __forceinline__ uint32_t smem_u32(const void* p) {
    uint32_t addr;
    asm("{ .reg .u64 t; cvta.to.shared.u64 t, %1; cvt.u32.u64 %0, t; }"
        : "=r"(addr) : "l"(p));
    return addr;
}

#define MMA_TF32(C, a0, a1, a2, a3, b0, b1)                                   \
    asm("mma.sync.aligned.m16n8k8.row.col.f32.tf32.tf32.f32 "                 \
        "{%0,%1,%2,%3}, {%4,%5,%6,%7}, {%8,%9}, {%0,%1,%2,%3};"               \
        : "+f"(C[0]), "+f"(C[1]), "+f"(C[2]), "+f"(C[3])                      \
        : "r"(a0), "r"(a1), "r"(a2), "r"(a3), "r"(b0), "r"(b1))

#define MBAR_WAIT_P0(mb)                                                       \
    do {                                                                       \
        uint32_t _done;                                                        \
        asm volatile(                                                          \
            "{\n\t.reg .pred p;\n\t"                                           \
            "mbarrier.try_wait.parity.acquire.cta.shared::cta.b64 p, [%1], 0;\n\t" \
            "selp.b32 %0, 1, 0, p;\n\t}"                                       \
            : "=r"(_done) : "r"(mb) : "memory");                               \
        if (!_done) {                                                          \
            asm volatile(                                                      \
                "{\n\t.reg .pred P1;\n\t"                                      \
                "W_%=:\n\t"                                                    \
                "mbarrier.try_wait.parity.acquire.cta.shared::cta.b64 P1, [%0], 0, 0x989680;\n\t" \
                "@P1 bra.uni D_%=;\n\t"                                        \
                "bra.uni W_%=;\n\t"                                            \
                "D_%=:\n\t}"                                                   \
                :: "r"(mb) : "memory");                                        \
        }                                                                      \
    } while (0)

// Cold path: exact reference emulation (proven R3/R6-R14).
__device__ __noinline__ int decide_exact(const float* __restrict__ zrow,
                                         const float* __restrict__ bs,
                                         int lane)
{
    int bi = 0;
    if (lane == 0) {
        float e[DC];
#pragma unroll 1
        for (int c = 0; c < DC - 1; c++) {
            double sd = 0.0;
#pragma unroll 1
            for (int d = 0; d < DZ; d++)
                sd += (double)zrow[d] * (double)bs[c * BS_STRIDE + d];
            float lf = (float)sd;
            e[c] = (float)exp((double)lf);
        }
        e[DC - 1] = 1.0f;
        float se = e[0];
#pragma unroll 1
        for (int c = 1; c < DC - 1; c++) se += e[c];
        const float norm = 1.0f + se;
        float pb = -1.0f;
#pragma unroll 1
        for (int c = 0; c < DC; c++) {
            float p = __fdiv_rn(e[c], norm);
            if (p > pb) { pb = p; bi = c; }   // strict > = first index
        }
    }
    return __shfl_sync(0xffffffffu, bi, 0);
}

// One tile's compute+decide+store. Byte-identical logic to R14 (proven).
__device__ __forceinline__ void process_tile(const float* __restrict__ zs,
                                             const float* __restrict__ bs,
                                             float* __restrict__ out,
                                             int rowBase, int T,
                                             int lane, int w, int a, int g)
{
    const int rw0 = w * 16;      // this warp's 16-row m-tile

    float C[4][4];
#pragma unroll
    for (int nt = 0; nt < 4; nt++)
#pragma unroll
        for (int j = 0; j < 4; j++) C[nt][j] = 0.0f;

#pragma unroll
    for (int kt = 0; kt < 8; kt++) {
        const int k0 = kt * 8 + a;

        uint32_t b0[4], b1[4];
#pragma unroll
        for (int nt = 0; nt < 4; nt++) {
            const int n = nt * 8 + g;
            float f0 = (n < DC - 1) ? bs[n * BS_STRIDE + k0]     : 0.0f;
            float f1 = (n < DC - 1) ? bs[n * BS_STRIDE + k0 + 4] : 0.0f;
            b0[nt] = to_tf32(f0);
            b1[nt] = to_tf32(f1);
        }

        const int r0 = rw0 + g;
        uint32_t a0 = to_tf32(zs[r0 * ZS_STRIDE + k0]);
        uint32_t a1 = to_tf32(zs[(r0 + 8) * ZS_STRIDE + k0]);
        uint32_t a2 = to_tf32(zs[r0 * ZS_STRIDE + k0 + 4]);
        uint32_t a3 = to_tf32(zs[(r0 + 8) * ZS_STRIDE + k0 + 4]);
#pragma unroll
        for (int nt = 0; nt < 4; nt++)
            MMA_TF32(C[nt], a0, a1, a2, a3, b0[nt], b1[nt]);
    }

    int idxs[2];
    unsigned flagm[2];
#pragma unroll
    for (int h = 0; h < 2; h++) {
        float best = C[0][h * 2];
        int   bch  = 2 * a;
#pragma unroll
        for (int nt = 0; nt < 4; nt++)
#pragma unroll
            for (int j = 0; j < 2; j++) {
                float v = C[nt][h * 2 + j];
                int  ch = nt * 8 + 2 * a + j;
                if (v > best) { best = v; bch = ch; }
            }
#pragma unroll
        for (int off = 1; off <= 2; off <<= 1) {
            float ov = __shfl_xor_sync(0xffffffffu, best, off);
            int   oc = __shfl_xor_sync(0xffffffffu, bch,  off);
            if (ov > best) { best = ov; bch = oc; }
        }
        int cnt = 0;
        const float th = best - TH_FAST;
#pragma unroll
        for (int nt = 0; nt < 4; nt++)
#pragma unroll
            for (int j = 0; j < 2; j++)
                cnt += (C[nt][h * 2 + j] >= th);
        cnt += __shfl_xor_sync(0xffffffffu, cnt, 1);
        cnt += __shfl_xor_sync(0xffffffffu, cnt, 2);

        idxs[h]  = bch;
        flagm[h] = __ballot_sync(0xffffffffu, cnt > 1);
    }

#pragma unroll 1
    for (int h = 0; h < 2; h++) {
        unsigned m = flagm[h] & 0x11111111u;
#pragma unroll 1
        while (m) {
            const int b = __ffs(m) - 1;
            m &= m - 1;
            const int q    = b >> 2;
            const int rloc = rw0 + q + h * 8;
            const int gr   = rowBase + rloc;
            if (gr >= T) continue;

            const float* zrow = &zs[rloc * ZS_STRIDE];

            float l = 0.0f;
            if (lane < DC - 1) {
                const float* br = &bs[lane * BS_STRIDE];
                float s0 = 0.0f, s1 = 0.0f;
#pragma unroll
                for (int q2 = 0; q2 < 16; q2++) {
                    float4 zq = *reinterpret_cast<const float4*>(&zrow[4 * q2]);
                    s0 = fmaf(zq.x, br[4 * q2 + 0], s0);
                    s1 = fmaf(zq.y, br[4 * q2 + 1], s1);
                    s0 = fmaf(zq.z, br[4 * q2 + 2], s0);
                    s1 = fmaf(zq.w, br[4 * q2 + 3], s1);
                }
                l = s0 + s1;
            }
            unsigned u = __float_as_uint(l);
            u = (u & 0x80000000u) ? ~u : (u | 0x80000000u);
            unsigned umax;
            asm("redux.sync.max.u32 %0, %1, 0xffffffff;" : "=r"(umax) : "r"(u));
            const float mx = (umax & 0x80000000u)
                               ? __uint_as_float(umax ^ 0x80000000u)
                               : __uint_as_float(~umax);
            const unsigned nearMask = __ballot_sync(0xffffffffu, l >= mx - TH_MED);
            int idx;
            if (__popc(nearMask) == 1) {
                idx = __ffs(nearMask) - 1;
            } else {
                idx = decide_exact(zrow, bs, lane);
            }
            if (g == q) idxs[h] = idx;
        }
    }

#pragma unroll
    for (int h = 0; h < 2; h++) {
        const int rloc = rw0 + g + h * 8;
        const int gr   = rowBase + rloc;
        if (gr < T) {
            float* o = out + (size_t)gr * DC + 2 * a;
#pragma unroll
            for (int nt = 0; nt < 4; nt++) {
                const int ch0 = nt * 8 + 2 * a;
                float2 v;
                v.x = (ch0     == idxs[h]) ? 1.0f : 0.0f;
                v.y = (ch0 + 1 == idxs[h]) ? 1.0f : 0.0f;
                *reinterpret_cast<float2*>(o + nt * 8) = v;
            }
        }
    }
}

__global__ __launch_bounds__(THREADS, 2)
void dec_cat_kernel(const float* __restrict__ Z,
                    const float* __restrict__ beta,
                    float* __restrict__ out,
                    int T)
{
    extern __shared__ char smem[];
    unsigned long long* mbar = reinterpret_cast<unsigned long long*>(smem + SM_MBAR);
    float* bs  = reinterpret_cast<float*>(smem + SM_BS);
    float* zs0 = reinterpret_cast<float*>(smem + SM_ZS0);
    float* zs1 = reinterpret_cast<float*>(smem + SM_ZS1);

    const int tid  = threadIdx.x;
    const int lane = tid & 31;
    const int w    = tid >> 5;
    const int a    = lane & 3;
    const int g    = lane >> 2;

    const int rowBase0 = blockIdx.x * (2 * TILE);
    const int rowBase1 = rowBase0 + TILE;
    const int rows0 = max(0, min(TILE, T - rowBase0));
    const int rows1 = max(0, min(TILE, T - rowBase1));

    const uint32_t mb0 = smem_u32(&mbar[0]);
    const uint32_t mb1 = smem_u32(&mbar[1]);

    // ---- init + arm both mbarriers (each used exactly once: parity 0) ----
    if (tid == 0) {
        asm volatile("mbarrier.init.shared.b64 [%0], 1;" :: "r"(mb0) : "memory");
        asm volatile("mbarrier.init.shared.b64 [%0], 1;" :: "r"(mb1) : "memory");
    }
    __syncthreads();
    if (tid == 0) {
        const uint32_t bytes0 = (uint32_t)rows0 * 256u + (DC - 1) * 256u;
        const uint32_t bytes1 = (uint32_t)rows1 * 256u;
        asm volatile("mbarrier.arrive.expect_tx.shared.b64 _, [%0], %1;"
                     :: "r"(mb0), "r"(bytes0) : "memory");
        asm volatile("mbarrier.arrive.expect_tx.shared.b64 _, [%0], %1;"
                     :: "r"(mb1), "r"(bytes1) : "memory");
    }
    __syncthreads();     // arms visible before any complete_tx can land

    // ---- issue all bulk copies: tile0 z + beta -> mb0, tile1 z -> mb1 ----
    if (tid < rows0) {
        uint32_t dst = smem_u32(&zs0[tid * ZS_STRIDE]);
        const float* src = Z + (size_t)(rowBase0 + tid) * DZ;
        asm volatile(
            "cp.async.bulk.shared::cta.global.mbarrier::complete_tx::bytes "
            "[%0], [%1], 256, [%2];"
            :: "r"(dst), "l"(src), "r"(mb0) : "memory");
    } else if (tid >= 128 && tid < 128 + DC - 1) {
        const int c = tid - 128;
        uint32_t dst = smem_u32(&bs[c * BS_STRIDE]);
        const float* src = beta + (size_t)c * DZ;
        asm volatile(
            "cp.async.bulk.shared::cta.global.mbarrier::complete_tx::bytes "
            "[%0], [%1], 256, [%2];"
            :: "r"(dst), "l"(src), "r"(mb0) : "memory");
    }
    if (tid >= 96 && tid - 96 < rows1) {      // different thread range spreads issue
        const int r = tid - 96;
        uint32_t dst = smem_u32(&zs1[r * ZS_STRIDE]);
        const float* src = Z + (size_t)(rowBase1 + r) * DZ;
        asm volatile(
            "cp.async.bulk.shared::cta.global.mbarrier::complete_tx::bytes "
            "[%0], [%1], 256, [%2];"
            :: "r"(dst), "l"(src), "r"(mb1) : "memory");
    }

    // ---- tile 0 ----
    if (rows0 > 0) {
        MBAR_WAIT_P0(mb0);
        process_tile(zs0, bs, out, rowBase0, T, lane, w, a, g);
    }

    // ---- tile 1 (its DRAM fetch overlapped tile 0 entirely) ----
    if (rows1 > 0) {
        MBAR_WAIT_P0(mb1);
        process_tile(zs1, bs, out, rowBase1, T, lane, w, a, g);
    }
}

extern "C" void kernel_launch(void* const* d_in, const int* in_sizes, int n_in,
                              void* d_out, int out_size)
{
    const float* Z    = (const float*)d_in[0];
    const float* beta = (const float*)d_in[1];
    float* out        = (float*)d_out;

    const int T = in_sizes[0] / DZ;
    const int grid = (T + 2 * TILE - 1) / (2 * TILE);

    cudaFuncSetAttribute(dec_cat_kernel,
                         cudaFuncAttributeMaxDynamicSharedMemorySize, SM_TOTAL);
    dec_cat_kernel<<<grid, THREADS, SM_TOTAL>>>(Z, beta, out, T);
}

// round 16
// speedup vs baseline: 5.6839x; 5.6839x over previous
#include <cuda_runtime.h>
#include <math.h>
#include <stdint.h>

#define DZ 64
#define DC 32
#define TILE 128
#define THREADS 256
#define ZS_STRIDE 68          // floats/row: conflict-free A-frag loads (4g+a distinct)
#define BS_STRIDE 68          // bank(4g+a) all-distinct for B loads
#define TH_FAST 2.5e-4f       // tf32 -> exact-fp32 re-decide trigger (proven R7-R14)
#define TH_MED  4e-6f         // fp32 -> exact re-decide trigger (proven R6-R14)

__device__ __forceinline__ uint32_t to_tf32(float f) {
    uint32_t r;
    asm("cvt.rna.tf32.f32 %0, %1;" : "=r"(r) : "f"(f));
    return r;
}

__device__ __forceinline__ uint32_t smem_u32(const void* p) {
    uint32_t addr;
    asm("{ .reg .u64 t; cvta.to.shared.u64 t, %1; cvt.u32.u64 %0, t; }"
        : "=r"(addr) : "l"(p));
    return addr;
}

#define MMA_TF32(C, a0, a1, a2, a3, b0, b1)                                   \
    asm("mma.sync.aligned.m16n8k8.row.col.f32.tf32.tf32.f32 "                 \
        "{%0,%1,%2,%3}, {%4,%5,%6,%7}, {%8,%9}, {%0,%1,%2,%3};"               \
        : "+f"(C[0]), "+f"(C[1]), "+f"(C[2]), "+f"(C[3])                      \
        : "r"(a0), "r"(a1), "r"(a2), "r"(a3), "r"(b0), "r"(b1))

// Cold path: exact reference emulation — LANE-PARALLEL restructuring of the
// proven (R3/R6-R14) serial version. Identical arithmetic:
//   per-channel double accumulation in the SAME d-order (fp32*fp32 products
//   are exact in double) -> fp32 logit -> double exp -> fp32 e
//   -> sequential fp32 norm in reference index order -> IEEE divide
//   -> first-index argmax (exact-equality ballot == strict-> serial scan).
__device__ __noinline__ int decide_exact(const float* __restrict__ zrow,
                                         const float* __restrict__ bs,
                                         int lane)
{
    float ef;
    if (lane < DC - 1) {
        const float* br = &bs[lane * BS_STRIDE];
        double sd = 0.0;
#pragma unroll 1
        for (int d = 0; d < DZ; d++)
            sd += (double)zrow[d] * (double)br[d];
        float lf = (float)sd;
        ef = (float)exp((double)lf);
    } else {
        ef = 1.0f;               // implicit channel 31
    }

    // sequential norm, reference order: se = e[0]; se += e[1] ... ; norm = 1+se
    float se = 0.0f;
#pragma unroll 1
    for (int c = 0; c < DC - 1; c++) {
        se += __shfl_sync(0xffffffffu, ef, c);
    }
    const float norm = 1.0f + se;

    const float p = __fdiv_rn(ef, norm);      // lane31 -> 1/norm (ref last col)

    // first-index argmax over p: p>0 so (bits | signbit) is strictly monotone;
    // equal p <-> equal encoding; ballot+ffs picks the lowest channel.
    unsigned u = __float_as_uint(p) | 0x80000000u;
    unsigned umax;
    asm("redux.sync.max.u32 %0, %1, 0xffffffff;" : "=r"(umax) : "r"(u));
    const unsigned win = __ballot_sync(0xffffffffu, u == umax);
    return __ffs(win) - 1;
}

__global__ __launch_bounds__(THREADS, 4)
void dec_cat_kernel(const float* __restrict__ Z,
                    const float* __restrict__ beta,
                    float* __restrict__ out,
                    int T)
{
    __shared__ alignas(128) float zs[TILE * ZS_STRIDE];       // z tile (34 KB)
    __shared__ alignas(128) float bs[(DC - 1) * BS_STRIDE];   // beta (8.4 KB)
    __shared__ alignas(8) unsigned long long mbar;

    const int tid  = threadIdx.x;
    const int lane = tid & 31;
    const int w    = tid >> 5;    // 8 warps
    const int a    = lane & 3;    // threadID in group
    const int g    = lane >> 2;   // groupID (quad)
    const int rowBase = blockIdx.x * TILE;
    const int rowsHere = min(TILE, T - rowBase);

    const uint32_t mb = smem_u32(&mbar);

    // ---- staging: one 256B cp.async.bulk per row (z + beta), one mbarrier ----
    if (tid == 0) {
        asm volatile("mbarrier.init.shared.b64 [%0], 1;" :: "r"(mb) : "memory");
    }
    __syncthreads();
    if (tid == 0) {
        const uint32_t totalBytes = (uint32_t)rowsHere * 256u + (DC - 1) * 256u;
        asm volatile("mbarrier.arrive.expect_tx.shared.b64 _, [%0], %1;"
                     :: "r"(mb), "r"(totalBytes) : "memory");
    }
    __syncthreads();     // expect_tx visible before any complete_tx can land

    if (tid < rowsHere) {
        uint32_t dst = smem_u32(&zs[tid * ZS_STRIDE]);
        const float* src = Z + (size_t)(rowBase + tid) * DZ;
        asm volatile(
            "cp.async.bulk.shared::cta.global.mbarrier::complete_tx::bytes "
            "[%0], [%1], 256, [%2];"
            :: "r"(dst), "l"(src), "r"(mb) : "memory");
    } else if (tid >= 128 && tid < 128 + DC - 1) {
        const int c = tid - 128;
        uint32_t dst = smem_u32(&bs[c * BS_STRIDE]);
        const float* src = beta + (size_t)c * DZ;
        asm volatile(
            "cp.async.bulk.shared::cta.global.mbarrier::complete_tx::bytes "
            "[%0], [%1], 256, [%2];"
            :: "r"(dst), "l"(src), "r"(mb) : "memory");
    }

    // wait for all bytes (parity 0)
    {
        uint32_t done;
        asm volatile(
            "{\n\t.reg .pred p;\n\t"
            "mbarrier.try_wait.parity.acquire.cta.shared::cta.b64 p, [%1], 0;\n\t"
            "selp.b32 %0, 1, 0, p;\n\t}"
            : "=r"(done) : "r"(mb) : "memory");
        if (!done) {
            asm volatile(
                "{\n\t.reg .pred P1;\n\t"
                "W_%=:\n\t"
                "mbarrier.try_wait.parity.acquire.cta.shared::cta.b64 P1, [%0], 0, 0x989680;\n\t"
                "@P1 bra.uni D_%=;\n\t"
                "bra.uni W_%=;\n\t"
                "D_%=:\n\t}"
                :: "r"(mb) : "memory");
        }
    }

    const int rw0 = w * 16;      // this warp's 16-row m-tile

    // ---- mainloop: 16x32x64 warp GEMM; B loaded per-kt from smem ----
    float C[4][4];
#pragma unroll
    for (int nt = 0; nt < 4; nt++)
#pragma unroll
        for (int j = 0; j < 4; j++) C[nt][j] = 0.0f;

#pragma unroll
    for (int kt = 0; kt < 8; kt++) {
        const int k0 = kt * 8 + a;

        uint32_t b0[4], b1[4];
#pragma unroll
        for (int nt = 0; nt < 4; nt++) {
            const int n = nt * 8 + g;
            float f0 = (n < DC - 1) ? bs[n * BS_STRIDE + k0]     : 0.0f;
            float f1 = (n < DC - 1) ? bs[n * BS_STRIDE + k0 + 4] : 0.0f;
            b0[nt] = to_tf32(f0);
            b1[nt] = to_tf32(f1);
        }

        const int r0 = rw0 + g;
        uint32_t a0 = to_tf32(zs[r0 * ZS_STRIDE + k0]);
        uint32_t a1 = to_tf32(zs[(r0 + 8) * ZS_STRIDE + k0]);
        uint32_t a2 = to_tf32(zs[r0 * ZS_STRIDE + k0 + 4]);
        uint32_t a3 = to_tf32(zs[(r0 + 8) * ZS_STRIDE + k0 + 4]);
#pragma unroll
        for (int nt = 0; nt < 4; nt++)
            MMA_TF32(C[nt], a0, a1, a2, a3, b0[nt], b1[nt]);
    }

    // ---- epilogue: 2 row-slots (h), argmax + ambiguity flagging (proven) ----
    int idxs[2];
    unsigned flagm[2];
#pragma unroll
    for (int h = 0; h < 2; h++) {
        float best = C[0][h * 2];
        int   bch  = 2 * a;
#pragma unroll
        for (int nt = 0; nt < 4; nt++)
#pragma unroll
            for (int j = 0; j < 2; j++) {
                float v = C[nt][h * 2 + j];
                int  ch = nt * 8 + 2 * a + j;
                if (v > best) { best = v; bch = ch; }
            }
#pragma unroll
        for (int off = 1; off <= 2; off <<= 1) {
            float ov = __shfl_xor_sync(0xffffffffu, best, off);
            int   oc = __shfl_xor_sync(0xffffffffu, bch,  off);
            if (ov > best) { best = ov; bch = oc; }
        }
        int cnt = 0;
        const float th = best - TH_FAST;
#pragma unroll
        for (int nt = 0; nt < 4; nt++)
#pragma unroll
            for (int j = 0; j < 2; j++)
                cnt += (C[nt][h * 2 + j] >= th);
        cnt += __shfl_xor_sync(0xffffffffu, cnt, 1);
        cnt += __shfl_xor_sync(0xffffffffu, cnt, 2);

        idxs[h]  = bch;
        flagm[h] = __ballot_sync(0xffffffffu, cnt > 1);
    }

    // ---- re-decide flagged rows (medium exact-fp32, then exact) ----
#pragma unroll 1
    for (int h = 0; h < 2; h++) {
        unsigned m = flagm[h] & 0x11111111u;   // one representative bit per quad
#pragma unroll 1
        while (m) {
            const int b = __ffs(m) - 1;
            m &= m - 1;
            const int q    = b >> 2;
            const int rloc = rw0 + q + h * 8;     // this warp's row in the tile
            const int gr   = rowBase + rloc;
            if (gr >= T) continue;

            const float* zrow = &zs[rloc * ZS_STRIDE];

            float l = 0.0f;
            if (lane < DC - 1) {
                const float* br = &bs[lane * BS_STRIDE];
                float s0 = 0.0f, s1 = 0.0f;
#pragma unroll
                for (int q2 = 0; q2 < 16; q2++) {
                    float4 zq = *reinterpret_cast<const float4*>(&zrow[4 * q2]);
                    s0 = fmaf(zq.x, br[4 * q2 + 0], s0);
                    s1 = fmaf(zq.y, br[4 * q2 + 1], s1);
                    s0 = fmaf(zq.z, br[4 * q2 + 2], s0);
                    s1 = fmaf(zq.w, br[4 * q2 + 3], s1);
                }
                l = s0 + s1;
            }
            unsigned u = __float_as_uint(l);
            u = (u & 0x80000000u) ? ~u : (u | 0x80000000u);
            unsigned umax;
            asm("redux.sync.max.u32 %0, %1, 0xffffffff;" : "=r"(umax) : "r"(u));
            const float mx = (umax & 0x80000000u)
                               ? __uint_as_float(umax ^ 0x80000000u)
                               : __uint_as_float(~umax);
            const unsigned nearMask = __ballot_sync(0xffffffffu, l >= mx - TH_MED);
            int idx;
            if (__popc(nearMask) == 1) {
                idx = __ffs(nearMask) - 1;
            } else {
                idx = decide_exact(zrow, bs, lane);
            }
            if (g == q) idxs[h] = idx;
        }
    }

    // ---- one-hot stores: quad-parallel STG.64 ----
#pragma unroll
    for (int h = 0; h < 2; h++) {
        const int rloc = rw0 + g + h * 8;
        const int gr   = rowBase + rloc;
        if (gr < T) {
            float* o = out + (size_t)gr * DC + 2 * a;
#pragma unroll
            for (int nt = 0; nt < 4; nt++) {
                const int ch0 = nt * 8 + 2 * a;
                float2 v;
                v.x = (ch0     == idxs[h]) ? 1.0f : 0.0f;
                v.y = (ch0 + 1 == idxs[h]) ? 1.0f : 0.0f;
                *reinterpret_cast<float2*>(o + nt * 8) = v;
            }
        }
    }
}

extern "C" void kernel_launch(void* const* d_in, const int* in_sizes, int n_in,
                              void* d_out, int out_size)
{
    const float* Z    = (const float*)d_in[0];
    const float* beta = (const float*)d_in[1];
    float* out        = (float*)d_out;

    const int T = in_sizes[0] / DZ;
    const int grid = (T + TILE - 1) / TILE;

    dec_cat_kernel<<<grid, THREADS>>>(Z, beta, out, T);
}

// round 17
// speedup vs baseline: 5.7450x; 1.0108x over previous
#include <cuda_runtime.h>
#include <math.h>
#include <stdint.h>

#define DZ 64
#define DC 32
#define TILE 128
#define THREADS 256
#define ZS_STRIDE 68          // floats/row: conflict-free A-frag loads (4g+a distinct)
#define BS_STRIDE 68          // bank(4g+a) all-distinct for B loads
#define BH_STRIDE 68          // same conflict-free pattern for tf32 B plane
#define TH_FAST 2.5e-4f       // tf32 -> exact-fp32 re-decide trigger (proven R7-R16)
#define TH_MED  4e-6f         // fp32 -> exact re-decide trigger (proven R6-R16)

// dynamic smem layout (bytes)
#define SM_ZS    0                         // 128*68*4 = 34816
#define SM_BS    34816                     // 31*68*4  = 8432
#define SM_BH    (34816 + 8432)            // 32*68*4  = 8704 (row 31 zeros)
#define SM_MBAR  (SM_BH + 8704)            // 8
#define SM_TOTAL (SM_MBAR + 128)

__device__ __forceinline__ uint32_t to_tf32(float f) {
    uint32_t r;
    asm("cvt.rna.tf32.f32 %0, %1;" : "=r"(r) : "f"(f));
    return r;
}

__device__ __forceinline__ uint32_t smem_u32(const void* p) {
    uint32_t addr;
    asm("{ .reg .u64 t; cvta.to.shared.u64 t, %1; cvt.u32.u64 %0, t; }"
        : "=r"(addr) : "l"(p));
    return addr;
}

#define MMA_TF32(C, a0, a1, a2, a3, b0, b1)                                   \
    asm("mma.sync.aligned.m16n8k8.row.col.f32.tf32.tf32.f32 "                 \
        "{%0,%1,%2,%3}, {%4,%5,%6,%7}, {%8,%9}, {%0,%1,%2,%3};"               \
        : "+f"(C[0]), "+f"(C[1]), "+f"(C[2]), "+f"(C[3])                      \
        : "r"(a0), "r"(a1), "r"(a2), "r"(a3), "r"(b0), "r"(b1))

// Cold path: exact reference emulation, lane-parallel (proven R16).
__device__ __noinline__ int decide_exact(const float* __restrict__ zrow,
                                         const float* __restrict__ bs,
                                         int lane)
{
    float ef;
    if (lane < DC - 1) {
        const float* br = &bs[lane * BS_STRIDE];
        double sd = 0.0;
#pragma unroll 1
        for (int d = 0; d < DZ; d++)
            sd += (double)zrow[d] * (double)br[d];
        float lf = (float)sd;
        ef = (float)exp((double)lf);
    } else {
        ef = 1.0f;               // implicit channel 31
    }

    float se = 0.0f;
#pragma unroll 1
    for (int c = 0; c < DC - 1; c++) {
        se += __shfl_sync(0xffffffffu, ef, c);
    }
    const float norm = 1.0f + se;

    const float p = __fdiv_rn(ef, norm);

    unsigned u = __float_as_uint(p) | 0x80000000u;
    unsigned umax;
    asm("redux.sync.max.u32 %0, %1, 0xffffffff;" : "=r"(umax) : "r"(u));
    const unsigned win = __ballot_sync(0xffffffffu, u == umax);
    return __ffs(win) - 1;
}

__global__ __launch_bounds__(THREADS, 4)
void dec_cat_kernel(const float* __restrict__ Z,
                    const float* __restrict__ beta,
                    float* __restrict__ out,
                    int T)
{
    extern __shared__ char smem[];
    float*    zs  = reinterpret_cast<float*>(smem + SM_ZS);
    float*    bs  = reinterpret_cast<float*>(smem + SM_BS);
    uint32_t* bh  = reinterpret_cast<uint32_t*>(smem + SM_BH);
    unsigned long long* mbar = reinterpret_cast<unsigned long long*>(smem + SM_MBAR);

    const int tid  = threadIdx.x;
    const int lane = tid & 31;
    const int w    = tid >> 5;    // 8 warps
    const int a    = lane & 3;    // threadID in group
    const int g    = lane >> 2;   // groupID (quad)
    const int rowBase = blockIdx.x * TILE;
    const int rowsHere = min(TILE, T - rowBase);

    const uint32_t mb = smem_u32(mbar);

    // ---- staging: one 256B cp.async.bulk per row (z + beta), one mbarrier ----
    if (tid == 0) {
        asm volatile("mbarrier.init.shared.b64 [%0], 1;" :: "r"(mb) : "memory");
    }
    __syncthreads();
    if (tid == 0) {
        const uint32_t totalBytes = (uint32_t)rowsHere * 256u + (DC - 1) * 256u;
        asm volatile("mbarrier.arrive.expect_tx.shared.b64 _, [%0], %1;"
                     :: "r"(mb), "r"(totalBytes) : "memory");
    }
    __syncthreads();     // expect_tx visible before any complete_tx can land

    if (tid < rowsHere) {
        uint32_t dst = smem_u32(&zs[tid * ZS_STRIDE]);
        const float* src = Z + (size_t)(rowBase + tid) * DZ;
        asm volatile(
            "cp.async.bulk.shared::cta.global.mbarrier::complete_tx::bytes "
            "[%0], [%1], 256, [%2];"
            :: "r"(dst), "l"(src), "r"(mb) : "memory");
    } else if (tid >= 128 && tid < 128 + DC - 1) {
        const int c = tid - 128;
        uint32_t dst = smem_u32(&bs[c * BS_STRIDE]);
        const float* src = beta + (size_t)c * DZ;
        asm volatile(
            "cp.async.bulk.shared::cta.global.mbarrier::complete_tx::bytes "
            "[%0], [%1], 256, [%2];"
            :: "r"(dst), "l"(src), "r"(mb) : "memory");
    }

    // wait for all bytes (parity 0)
    {
        uint32_t done;
        asm volatile(
            "{\n\t.reg .pred p;\n\t"
            "mbarrier.try_wait.parity.acquire.cta.shared::cta.b64 p, [%1], 0;\n\t"
            "selp.b32 %0, 1, 0, p;\n\t}"
            : "=r"(done) : "r"(mb) : "memory");
        if (!done) {
            asm volatile(
                "{\n\t.reg .pred P1;\n\t"
                "W_%=:\n\t"
                "mbarrier.try_wait.parity.acquire.cta.shared::cta.b64 P1, [%0], 0, 0x989680;\n\t"
                "@P1 bra.uni D_%=;\n\t"
                "bra.uni W_%=;\n\t"
                "D_%=:\n\t}"
                :: "r"(mb) : "memory");
        }
    }

    // ---- build pre-converted tf32 B plane (row 31 = zeros). Same fp32 input
    //      -> same cvt.rna bits -> fast path bit-identical to R16. ----
    for (int i = tid; i < DC * DZ; i += THREADS) {
        const int n = i >> 6, k = i & 63;
        const float f = (n < DC - 1) ? bs[n * BS_STRIDE + k] : 0.0f;
        bh[n * BH_STRIDE + k] = to_tf32(f);
    }
    __syncthreads();

    const int rw0 = w * 16;      // this warp's 16-row m-tile

    // ---- mainloop: 16x32x64 warp GEMM; B = bare LDS from tf32 plane ----
    float C[4][4];
#pragma unroll
    for (int nt = 0; nt < 4; nt++)
#pragma unroll
        for (int j = 0; j < 4; j++) C[nt][j] = 0.0f;

#pragma unroll
    for (int kt = 0; kt < 8; kt++) {
        const int k0 = kt * 8 + a;

        uint32_t b0[4], b1[4];
#pragma unroll
        for (int nt = 0; nt < 4; nt++) {
            const uint32_t* bp = &bh[(nt * 8 + g) * BH_STRIDE + k0];
            b0[nt] = bp[0];
            b1[nt] = bp[4];
        }

        const int r0 = rw0 + g;
        uint32_t a0 = to_tf32(zs[r0 * ZS_STRIDE + k0]);
        uint32_t a1 = to_tf32(zs[(r0 + 8) * ZS_STRIDE + k0]);
        uint32_t a2 = to_tf32(zs[r0 * ZS_STRIDE + k0 + 4]);
        uint32_t a3 = to_tf32(zs[(r0 + 8) * ZS_STRIDE + k0 + 4]);
#pragma unroll
        for (int nt = 0; nt < 4; nt++)
            MMA_TF32(C[nt], a0, a1, a2, a3, b0[nt], b1[nt]);
    }

    // ---- epilogue: 2 row-slots (h), argmax + ambiguity flagging (proven) ----
    int idxs[2];
    unsigned flagm[2];
#pragma unroll
    for (int h = 0; h < 2; h++) {
        float best = C[0][h * 2];
        int   bch  = 2 * a;
#pragma unroll
        for (int nt = 0; nt < 4; nt++)
#pragma unroll
            for (int j = 0; j < 2; j++) {
                float v = C[nt][h * 2 + j];
                int  ch = nt * 8 + 2 * a + j;
                if (v > best) { best = v; bch = ch; }
            }
#pragma unroll
        for (int off = 1; off <= 2; off <<= 1) {
            float ov = __shfl_xor_sync(0xffffffffu, best, off);
            int   oc = __shfl_xor_sync(0xffffffffu, bch,  off);
            if (ov > best) { best = ov; bch = oc; }
        }
        int cnt = 0;
        const float th = best - TH_FAST;
#pragma unroll
        for (int nt = 0; nt < 4; nt++)
#pragma unroll
            for (int j = 0; j < 2; j++)
                cnt += (C[nt][h * 2 + j] >= th);
        cnt += __shfl_xor_sync(0xffffffffu, cnt, 1);
        cnt += __shfl_xor_sync(0xffffffffu, cnt, 2);

        idxs[h]  = bch;
        flagm[h] = __ballot_sync(0xffffffffu, cnt > 1);
    }

    // ---- re-decide flagged rows (medium exact-fp32, then exact) ----
#pragma unroll 1
    for (int h = 0; h < 2; h++) {
        unsigned m = flagm[h] & 0x11111111u;   // one representative bit per quad
#pragma unroll 1
        while (m) {
            const int b = __ffs(m) - 1;
            m &= m - 1;
            const int q    = b >> 2;
            const int rloc = rw0 + q + h * 8;     // this warp's row in the tile
            const int gr   = rowBase + rloc;
            if (gr >= T) continue;

            const float* zrow = &zs[rloc * ZS_STRIDE];

            float l = 0.0f;
            if (lane < DC - 1) {
                const float* br = &bs[lane * BS_STRIDE];
                float s0 = 0.0f, s1 = 0.0f;
#pragma unroll
                for (int q2 = 0; q2 < 16; q2++) {
                    float4 zq = *reinterpret_cast<const float4*>(&zrow[4 * q2]);
                    s0 = fmaf(zq.x, br[4 * q2 + 0], s0);
                    s1 = fmaf(zq.y, br[4 * q2 + 1], s1);
                    s0 = fmaf(zq.z, br[4 * q2 + 2], s0);
                    s1 = fmaf(zq.w, br[4 * q2 + 3], s1);
                }
                l = s0 + s1;
            }
            unsigned u = __float_as_uint(l);
            u = (u & 0x80000000u) ? ~u : (u | 0x80000000u);
            unsigned umax;
            asm("redux.sync.max.u32 %0, %1, 0xffffffff;" : "=r"(umax) : "r"(u));
            const float mx = (umax & 0x80000000u)
                               ? __uint_as_float(umax ^ 0x80000000u)
                               : __uint_as_float(~umax);
            const unsigned nearMask = __ballot_sync(0xffffffffu, l >= mx - TH_MED);
            int idx;
            if (__popc(nearMask) == 1) {
                idx = __ffs(nearMask) - 1;
            } else {
                idx = decide_exact(zrow, bs, lane);
            }
            if (g == q) idxs[h] = idx;
        }
    }

    // ---- one-hot stores: remapped STG.128 — lane writes its quad's row at
    //      columns [4a,4a+4) and [4a+16,4a+20) (idx is quad-uniform) ----
#pragma unroll
    for (int h = 0; h < 2; h++) {
        const int rloc = rw0 + g + h * 8;
        const int gr   = rowBase + rloc;
        if (gr < T) {
            float* o = out + (size_t)gr * DC;
            const int idx = idxs[h];
#pragma unroll
            for (int half = 0; half < 2; half++) {
                const int c0 = 4 * a + 16 * half;
                float4 v;
                v.x = (c0 + 0 == idx) ? 1.0f : 0.0f;
                v.y = (c0 + 1 == idx) ? 1.0f : 0.0f;
                v.z = (c0 + 2 == idx) ? 1.0f : 0.0f;
                v.w = (c0 + 3 == idx) ? 1.0f : 0.0f;
                *reinterpret_cast<float4*>(o + c0) = v;
            }
        }
    }
}

extern "C" void kernel_launch(void* const* d_in, const int* in_sizes, int n_in,
                              void* d_out, int out_size)
{
    const float* Z    = (const float*)d_in[0];
    const float* beta = (const float*)d_in[1];
    float* out        = (float*)d_out;

    const int T = in_sizes[0] / DZ;
    const int grid = (T + TILE - 1) / TILE;

    cudaFuncSetAttribute(dec_cat_kernel,
                         cudaFuncAttributeMaxDynamicSharedMemorySize, SM_TOTAL);
    dec_cat_kernel<<<grid, THREADS, SM_TOTAL>>>(Z, beta, out, T);
}